// round 8
// baseline (speedup 1.0000x reference)
#include <cuda_runtime.h>
#include <cuda_fp16.h>
#include <math.h>
#include <stdint.h>

#define NIMG 16
#define CCH 256
#define NPIX 4096            // 64*64

// ---- scratch (static device globals; no allocation) ----
__device__ __half g_Qp[16777216];
__device__ __half g_Kp[16777216];
__device__ __half g_Vp[16777216];
__device__ float  g_S[2*2048*2048];
__device__ float  g_part[8388608];
__device__ float  g_xs1[NIMG*CCH*NPIX];
__device__ __half g_xsh [NIMG*CCH*NPIX];
__device__ __half g_atth[NIMG*CCH*NPIX];
__device__ __half g_xs1h[NIMG*CCH*NPIX];
__device__ __half g_ffh [NIMG*CCH*NPIX];
__device__ __half g_Wqh[65536], g_Wkh[65536], g_Wvh[65536];
__device__ __half g_Wlh[589824], g_Wf1h[589824], g_Wf2h[589824];   // tap-major

// ============================================================================
// helpers
// ============================================================================
__device__ __forceinline__ void mma16(float* d, const uint32_t* a, const uint32_t* b) {
    asm volatile(
        "mma.sync.aligned.m16n8k16.row.col.f32.f16.f16.f32 "
        "{%0,%1,%2,%3}, {%4,%5,%6,%7}, {%8,%9}, {%0,%1,%2,%3};"
        : "+f"(d[0]), "+f"(d[1]), "+f"(d[2]), "+f"(d[3])
        : "r"(a[0]), "r"(a[1]), "r"(a[2]), "r"(a[3]), "r"(b[0]), "r"(b[1]));
}

__device__ __forceinline__ void ldsm4(uint32_t* r, const void* p) {
    uint32_t addr = (uint32_t)__cvta_generic_to_shared(p);
    asm volatile("ldmatrix.sync.aligned.m8n8.x4.shared.b16 {%0,%1,%2,%3}, [%4];"
        : "=r"(r[0]), "=r"(r[1]), "=r"(r[2]), "=r"(r[3]) : "r"(addr));
}

__device__ __forceinline__ void ldsm4t(uint32_t* r, const void* p) {
    uint32_t addr = (uint32_t)__cvta_generic_to_shared(p);
    asm volatile("ldmatrix.sync.aligned.m8n8.x4.trans.shared.b16 {%0,%1,%2,%3}, [%4];"
        : "=r"(r[0]), "=r"(r[1]), "=r"(r[2]), "=r"(r[3]) : "r"(addr));
}

__device__ __forceinline__ uint32_t pack_h2(float a, float b) {
    __half2 h = __floats2half2_rn(a, b);
    return *(uint32_t*)&h;
}

__device__ __forceinline__ void cpa16(uint32_t dst, const void* src, unsigned sz) {
    asm volatile("cp.async.ca.shared.global [%0], [%1], 16, %2;"
                 :: "r"(dst), "l"(src), "r"(sz) : "memory");
}
__device__ __forceinline__ void cpcommit() {
    asm volatile("cp.async.commit_group;" ::: "memory");
}
template <int N>
__device__ __forceinline__ void cpwait() {
    asm volatile("cp.async.wait_group %0;" :: "n"(N) : "memory");
}

// f32 -> f16 bulk convert (exact multiples of 1024 elems)
__global__ void f2h_kernel(const float* __restrict__ src, __half* __restrict__ dst) {
    long i = ((long)blockIdx.x * 256 + threadIdx.x) * 4;
    float4 v = *(const float4*)(src + i);
    *(uint32_t*)(dst + i)     = pack_h2(v.x, v.y);
    *(uint32_t*)(dst + i + 2) = pack_h2(v.z, v.w);
}

// conv weight transpose+convert: W[oc][c][tap] f32 -> Wt2[oc][tap][c] half
__global__ void wtrans_kernel(const float* __restrict__ W, __half* __restrict__ Wt2) {
    int idx = blockIdx.x * 256 + threadIdx.x;
    int oc = idx / 2304, r = idx - oc * 2304;
    int tap = r >> 8, c = r & 255;
    Wt2[idx] = __float2half(W[oc * 2304 + c * 9 + tap]);
}

// scatter index into patchified buffer: scale = oc>>6
__device__ __forceinline__ long pat_index(int img, int oc, int pix) {
    int s  = oc >> 6, cc = oc & 63;
    int lp = 5 - s;
    int lo = 1 + s;
    int Pm = (1 << lp) - 1;
    int y = pix >> 6, x = pix & 63;
    int ohi = y >> lp, pi = y & Pm, owi = x >> lp, pj = x & Pm;
    int t = img & 7, b = img >> 3;
    int nn = (t << (2*lo)) + (ohi << lo) + owi;
    int dd = (cc << (2*lp)) + (pi << lp) + pj;
    return (long)s * 4194304 + (long)b * 2097152 + (long)nn * (64 << (2*lp)) + dd;
}

// ============================================================================
// hconv2 (ks==1 only now): QKV projection, cp.async pipelined, 256 threads
// ============================================================================
__global__ void __launch_bounds__(256, 2) hconv2_kernel(
    const __half* __restrict__ in, const __half* __restrict__ Wt,
    const float* __restrict__ bias, __half* __restrict__ outh_pat)
{
    __shared__ __half A2[2 * 128 * 40];
    __shared__ __half B2[2 * 32 * 136];

    const int tid = threadIdx.x;
    const int lane = tid & 31, wid = tid >> 5;
    const int wm = wid & 1, wn = wid >> 1;
    const int img = blockIdx.x >> 5;
    const int p0 = (blockIdx.x & 31) * 128;
    const int m0 = blockIdx.y * 128;
    const __half* inimg = in + (long)img * CCH * NPIX;

    const uint32_t sA2 = (uint32_t)__cvta_generic_to_shared(A2);
    const uint32_t sB2 = (uint32_t)__cvta_generic_to_shared(B2);

#define ISSUE1(KCN, NB)                                                         \
    {                                                                           \
        const int k0n = (KCN) * 32;                                             \
        {                                                                       \
            int row = tid >> 1, seg = (tid & 1) * 16;                           \
            const __half* src = Wt + (long)(m0 + row) * 256 + k0n + seg;        \
            uint32_t dst = sA2 + (uint32_t)(((NB) * 5120 + row * 40 + seg) * 2);\
            cpa16(dst, src, 16u); cpa16(dst + 16, src + 8, 16u);                \
        }                                                                       \
        {                                                                       \
            int k = tid >> 3, u = tid & 7;                                      \
            const __half* src = inimg + ((long)(k0n + k) << 12) + p0 + u * 8;   \
            uint32_t dst = sB2 + (uint32_t)(((NB) * 4352 + k * 136 + u * 8) * 2); \
            cpa16(dst, src, 16u);                                               \
            cpa16(dst + 128, src + 64, 16u);                                    \
        }                                                                       \
        cpcommit();                                                             \
    }

    float acc[4][4][4] = {};
    ISSUE1(0, 0);

    for (int kc = 0; kc < 8; kc++) {
        cpwait<0>();
        __syncthreads();
        if (kc + 1 < 8) ISSUE1(kc + 1, (kc + 1) & 1);

        const __half* Ap = A2 + (kc & 1) * 5120;
        const __half* Bp = B2 + (kc & 1) * 4352;
#pragma unroll
        for (int kstep = 0; kstep < 2; kstep++) {
            uint32_t a[4][4], b[4][2];
            {
                const int arow = wm * 64 + ((lane >> 3) & 1) * 8 + (lane & 7);
                const int akc  = kstep * 16 + (lane >> 4) * 8;
#pragma unroll
                for (int mi = 0; mi < 4; mi++)
                    ldsm4(a[mi], Ap + (arow + mi * 16) * 40 + akc);
            }
            {
                const int brow = kstep * 16 + (lane & 7) + ((lane >> 3) & 1) * 8;
#pragma unroll
                for (int ni2 = 0; ni2 < 2; ni2++) {
                    const int bcol = wn * 32 + ni2 * 16 + ((lane >> 4) & 1) * 8;
                    uint32_t r[4];
                    ldsm4t(r, Bp + brow * 136 + bcol);
                    b[2*ni2    ][0] = r[0]; b[2*ni2    ][1] = r[1];
                    b[2*ni2 + 1][0] = r[2]; b[2*ni2 + 1][1] = r[3];
                }
            }
#pragma unroll
            for (int mi = 0; mi < 4; mi++)
#pragma unroll
                for (int ni = 0; ni < 4; ni++)
                    mma16(acc[mi][ni], a[mi], b[ni]);
        }
        __syncthreads();
    }
#undef ISSUE1

    const int orow = m0 + wm * 64 + (lane >> 2);
    const int ocol = p0 + wn * 32 + (lane & 3) * 2;
#pragma unroll
    for (int mi = 0; mi < 4; mi++) {
        const int oca = orow + mi * 16, ocb = oca + 8;
        const float ba = bias[oca], bb = bias[ocb];
#pragma unroll
        for (int ni = 0; ni < 4; ni++) {
            const int n = ocol + ni * 8;
            long ia = pat_index(img, oca, n);
            long ib = pat_index(img, ocb, n);
            *(__half2*)(outh_pat + ia) = __floats2half2_rn(acc[mi][ni][0] + ba, acc[mi][ni][1] + ba);
            *(__half2*)(outh_pat + ib) = __floats2half2_rn(acc[mi][ni][2] + bb, acc[mi][ni][3] + bb);
        }
    }
}

// ============================================================================
// hconv3: 3x3 conv, tap-major K, 512 threads, M=128 x N=256 tile, cp.async
//   dynamic smem layout: A2[2*5120] | Bs[32*264] | Strip[32*320]
// ============================================================================
#define H3_A2    0
#define H3_BS    10240
#define H3_STRIP (10240 + 8448)
#define H3_SMEM  ((10240 + 8448 + 10240) * 2)

__global__ void __launch_bounds__(512, 1) hconv3_kernel(
    const __half* __restrict__ in, const __half* __restrict__ Wt,
    const float* __restrict__ bias, const float* __restrict__ res,
    float* __restrict__ out, __half* __restrict__ outh_img,
    int dil, int addres)
{
    extern __shared__ __half sh[];
    __half* A2    = sh + H3_A2;
    __half* Bs    = sh + H3_BS;
    __half* Strip = sh + H3_STRIP;

    const int tid = threadIdx.x;
    const int lane = tid & 31, wid = tid >> 5;
    const int wm = wid & 1, wn = wid >> 1;         // 2 x 8 warps
    const int img = blockIdx.x >> 4;
    const int p0 = (blockIdx.x & 15) * 256;
    const int y0 = p0 >> 6;                        // 4 rows y0..y0+3
    const int m0 = blockIdx.y * 128;
    const __half* inimg = in + (long)img * CCH * NPIX;

    const uint32_t sA2    = (uint32_t)__cvta_generic_to_shared(A2);
    const uint32_t sStrip = (uint32_t)__cvta_generic_to_shared(Strip);

    // zero strip halos once (256 threads cover 32c x 4r x 2 sides)
    if (tid < 256) {
        int c = tid >> 3, u = tid & 7, r = u >> 1, side = u & 1;
        *(uint4*)(Strip + c * 320 + r * 80 + side * 72) = make_uint4(0, 0, 0, 0);
    }

#define ISSUE3(KCN, NB)                                                         \
    {                                                                           \
        const int k0n = (KCN) * 32;                                             \
        {   /* A: 128 oc x 32 k */                                              \
            int row = tid >> 2, seg = (tid & 3) * 8;                            \
            const __half* src = Wt + (long)(m0 + row) * 2304 + k0n + seg;       \
            cpa16(sA2 + (uint32_t)(((NB) * 5120 + row * 40 + seg) * 2), src, 16u); \
        }                                                                       \
        {   /* strip: 32 ch x 4 rows x 64 px */                                 \
            int tap = k0n >> 8, c0 = k0n & 255;                                 \
            int dyd = (tap / 3 - 1) * dil;                                      \
            int c = tid >> 4, u = tid & 15;                                     \
            int r = u >> 2, s = u & 3;                                          \
            int gy = y0 + r + dyd;                                              \
            unsigned ok = ((unsigned)gy < 64u) ? 16u : 0u;                      \
            int gyc = gy < 0 ? 0 : (gy > 63 ? 63 : gy);                         \
            const __half* src = inimg + ((long)(c0 + c) << 12) + (gyc << 6) + s * 16; \
            uint32_t dst = sStrip + (uint32_t)((c * 320 + r * 80 + 8 + s * 16) * 2);  \
            cpa16(dst, src, ok);                                                \
            cpa16(dst + 16, src + 8, ok);                                       \
        }                                                                       \
        cpcommit();                                                             \
    }

    float acc[4][4][4] = {};
    ISSUE3(0, 0);

    for (int kc = 0; kc < 72; kc++) {
        cpwait<0>();
        __syncthreads();

        // build shifted B tile (32 ch x 256 px) from strip
        {
            int tap = (kc * 32) >> 8;
            int dxd = (tap - (tap / 3) * 3 - 1) * dil;
            int c = tid >> 4, u = tid & 15, prow = u >> 2, xseg = (u & 3) * 16;
            const __half* sp = Strip + c * 320 + prow * 80 + 8 + dxd + xseg;
            uint32_t w[8];
#pragma unroll
            for (int j = 0; j < 8; j++) {
                uint32_t lo = *(const uint16_t*)(sp + 2 * j);
                uint32_t hi = *(const uint16_t*)(sp + 2 * j + 1);
                w[j] = lo | (hi << 16);
            }
            uint4* bd = (uint4*)(Bs + c * 264 + prow * 64 + xseg);
            bd[0] = make_uint4(w[0], w[1], w[2], w[3]);
            bd[1] = make_uint4(w[4], w[5], w[6], w[7]);
        }
        __syncthreads();

        if (kc + 1 < 72) ISSUE3(kc + 1, (kc + 1) & 1);

        const __half* Ap = A2 + (kc & 1) * 5120;
#pragma unroll
        for (int kstep = 0; kstep < 2; kstep++) {
            uint32_t a[4][4], b[4][2];
            {
                const int arow = wm * 64 + ((lane >> 3) & 1) * 8 + (lane & 7);
                const int akc  = kstep * 16 + (lane >> 4) * 8;
#pragma unroll
                for (int mi = 0; mi < 4; mi++)
                    ldsm4(a[mi], Ap + (arow + mi * 16) * 40 + akc);
            }
            {
                const int brow = kstep * 16 + (lane & 7) + ((lane >> 3) & 1) * 8;
#pragma unroll
                for (int ni2 = 0; ni2 < 2; ni2++) {
                    const int bcol = wn * 32 + ni2 * 16 + ((lane >> 4) & 1) * 8;
                    uint32_t r[4];
                    ldsm4t(r, Bs + brow * 264 + bcol);
                    b[2*ni2    ][0] = r[0]; b[2*ni2    ][1] = r[1];
                    b[2*ni2 + 1][0] = r[2]; b[2*ni2 + 1][1] = r[3];
                }
            }
#pragma unroll
            for (int mi = 0; mi < 4; mi++)
#pragma unroll
                for (int ni = 0; ni < 4; ni++)
                    mma16(acc[mi][ni], a[mi], b[ni]);
        }
    }
#undef ISSUE3

    const int orow = m0 + wm * 64 + (lane >> 2);
    const int ocol = p0 + wn * 32 + (lane & 3) * 2;
#pragma unroll
    for (int mi = 0; mi < 4; mi++) {
        const int oca = orow + mi * 16;
        const int ocb = oca + 8;
        const float ba = bias[oca], bb = bias[ocb];
#pragma unroll
        for (int ni = 0; ni < 4; ni++) {
            const int n = ocol + ni * 8;
            long ia = ((long)img * 256 + oca) * NPIX + n;
            long ib = ((long)img * 256 + ocb) * NPIX + n;
            float v0 = acc[mi][ni][0] + ba, v1 = acc[mi][ni][1] + ba;
            float v2 = acc[mi][ni][2] + bb, v3 = acc[mi][ni][3] + bb;
            v0 = (v0 > 0.f) ? v0 : 0.2f * v0;
            v1 = (v1 > 0.f) ? v1 : 0.2f * v1;
            v2 = (v2 > 0.f) ? v2 : 0.2f * v2;
            v3 = (v3 > 0.f) ? v3 : 0.2f * v3;
            if (addres) {
                v0 += res[ia]; v1 += res[ia + 1];
                v2 += res[ib]; v3 += res[ib + 1];
            }
            if (out) {
                out[ia] = v0; out[ia + 1] = v1;
                out[ib] = v2; out[ib + 1] = v3;
            }
            if (outh_img) {
                *(__half2*)(outh_img + ia) = __floats2half2_rn(v0, v1);
                *(__half2*)(outh_img + ib) = __floats2half2_rn(v2, v3);
            }
        }
    }
}

// ============================================================================
// fp16 NT GEMM with deterministic split-K (scores), f32 out
// ============================================================================
__global__ void __launch_bounds__(256) hgemm_nt_kernel(
    const __half* __restrict__ A, const __half* __restrict__ B, float* __restrict__ C,
    int N, int K, int splitk, long sAB, long sC)
{
    __shared__ __half As[128 * 40];
    __shared__ __half Bs[128 * 40];
    const int tid = threadIdx.x;
    const int lane = tid & 31, wid = tid >> 5;
    const int wm = wid & 1, wn = wid >> 1;
    const int n0 = blockIdx.x * 128, m0 = blockIdx.y * 128;
    const int z = blockIdx.z, bat = z / splitk, ks = z - bat * splitk;
    A += (long)bat * sAB;
    B += (long)bat * sAB;
    C += (long)z * sC;
    const int kchunk = K / splitk, kbeg = ks * kchunk;
    const int wr = tid >> 1, wkh = (tid & 1) * 16;

    float acc[4][4][4] = {};
    for (int k0 = kbeg; k0 < kbeg + kchunk; k0 += 32) {
        __syncthreads();
        {
            const __half* sa = A + (long)(m0 + wr) * K + k0 + wkh;
            const __half* sb = B + (long)(n0 + wr) * K + k0 + wkh;
            *(uint4*)(As + wr * 40 + wkh)     = *(const uint4*)sa;
            *(uint4*)(As + wr * 40 + wkh + 8) = *(const uint4*)(sa + 8);
            *(uint4*)(Bs + wr * 40 + wkh)     = *(const uint4*)sb;
            *(uint4*)(Bs + wr * 40 + wkh + 8) = *(const uint4*)(sb + 8);
        }
        __syncthreads();
#pragma unroll
        for (int kstep = 0; kstep < 2; kstep++) {
            uint32_t a[4][4], b[4][2];
            {
                const int arow = wm * 64 + ((lane >> 3) & 1) * 8 + (lane & 7);
                const int akc  = kstep * 16 + (lane >> 4) * 8;
#pragma unroll
                for (int mi = 0; mi < 4; mi++)
                    ldsm4(a[mi], As + (arow + mi * 16) * 40 + akc);
            }
            {
                const int bkc = kstep * 16 + ((lane >> 3) & 1) * 8;
#pragma unroll
                for (int ni2 = 0; ni2 < 2; ni2++) {
                    const int brow = wn * 32 + ni2 * 16 + ((lane >> 4) & 1) * 8 + (lane & 7);
                    uint32_t r[4];
                    ldsm4(r, Bs + brow * 40 + bkc);
                    b[2*ni2    ][0] = r[0]; b[2*ni2    ][1] = r[1];
                    b[2*ni2 + 1][0] = r[2]; b[2*ni2 + 1][1] = r[3];
                }
            }
#pragma unroll
            for (int mi = 0; mi < 4; mi++)
#pragma unroll
                for (int ni = 0; ni < 4; ni++)
                    mma16(acc[mi][ni], a[mi], b[ni]);
        }
    }
    const int orow = m0 + wm * 64 + (lane >> 2);
    const int ocol = n0 + wn * 32 + (lane & 3) * 2;
#pragma unroll
    for (int mi = 0; mi < 4; mi++) {
        long ra = (long)(orow + mi * 16) * N;
        long rb = (long)(orow + mi * 16 + 8) * N;
#pragma unroll
        for (int ni = 0; ni < 4; ni++) {
            int n = ocol + ni * 8;
            C[ra + n] = acc[mi][ni][0]; C[ra + n + 1] = acc[mi][ni][1];
            C[rb + n] = acc[mi][ni][2]; C[rb + n + 1] = acc[mi][ni][3];
        }
    }
}

// ============================================================================
// fp16 AV GEMM (NN via trans-ldmatrix B), scatter epilogue -> half image
// ============================================================================
__global__ void __launch_bounds__(256) hgemm_av_kernel(
    const float* __restrict__ S, const __half* __restrict__ V, __half* __restrict__ out,
    int n, int d, int lp, int c0)
{
    __shared__ __half As[128 * 40];
    __shared__ __half Bs[32 * 136];
    const int tid = threadIdx.x;
    const int lane = tid & 31, wid = tid >> 5;
    const int wm = wid & 1, wn = wid >> 1;
    const int z = blockIdx.z;
    S += (long)z * n * n;
    V += (long)z * n * d;
    const int n0 = blockIdx.x * 128;
    const int m0 = blockIdx.y * 128;
    const int wr = tid >> 1, wkh = (tid & 1) * 16;
    const int bk = tid >> 3, bn0 = (tid & 7) * 16;

    float acc[4][4][4] = {};
    for (int k0 = 0; k0 < n; k0 += 32) {
        __syncthreads();
        {
            const float* sa = S + (long)(m0 + wr) * n + k0 + wkh;
            uint32_t* ad = (uint32_t*)(As + wr * 40 + wkh);
#pragma unroll
            for (int i4 = 0; i4 < 4; i4++) {
                float4 v = *(const float4*)(sa + i4 * 4);
                ad[i4*2 + 0] = pack_h2(v.x, v.y);
                ad[i4*2 + 1] = pack_h2(v.z, v.w);
            }
            const __half* sb = V + (long)(k0 + bk) * d + n0 + bn0;
            *(uint4*)(Bs + bk * 136 + bn0)     = *(const uint4*)sb;
            *(uint4*)(Bs + bk * 136 + bn0 + 8) = *(const uint4*)(sb + 8);
        }
        __syncthreads();
#pragma unroll
        for (int kstep = 0; kstep < 2; kstep++) {
            uint32_t a[4][4], b[4][2];
            {
                const int arow = wm * 64 + ((lane >> 3) & 1) * 8 + (lane & 7);
                const int akc  = kstep * 16 + (lane >> 4) * 8;
#pragma unroll
                for (int mi = 0; mi < 4; mi++)
                    ldsm4(a[mi], As + (arow + mi * 16) * 40 + akc);
            }
            {
                const int brow = kstep * 16 + (lane & 7) + ((lane >> 3) & 1) * 8;
#pragma unroll
                for (int ni2 = 0; ni2 < 2; ni2++) {
                    const int bcol = wn * 32 + ni2 * 16 + ((lane >> 4) & 1) * 8;
                    uint32_t r[4];
                    ldsm4t(r, Bs + brow * 136 + bcol);
                    b[2*ni2    ][0] = r[0]; b[2*ni2    ][1] = r[1];
                    b[2*ni2 + 1][0] = r[2]; b[2*ni2 + 1][1] = r[3];
                }
            }
#pragma unroll
            for (int mi = 0; mi < 4; mi++)
#pragma unroll
                for (int ni = 0; ni < 4; ni++)
                    mma16(acc[mi][ni], a[mi], b[ni]);
        }
    }

    const int lo = 6 - lp;
    const int orow = m0 + wm * 64 + (lane >> 2);
    const int ocol = n0 + wn * 32 + (lane & 3) * 2;
#pragma unroll
    for (int mi = 0; mi < 4; mi++) {
#pragma unroll
        for (int hf = 0; hf < 2; hf++) {
            const int m = orow + mi * 16 + hf * 8;
            const int t = m >> (2 * lo);
            const int r = m & ((1 << (2 * lo)) - 1);
            const int ohi = r >> lo, owi = r & ((1 << lo) - 1);
#pragma unroll
            for (int ni = 0; ni < 4; ni++) {
                const int col = ocol + ni * 8;
                const int cc = col >> (2 * lp);
                const int rr = col & ((1 << (2 * lp)) - 1);
                const int pi = rr >> lp, pj = rr & ((1 << lp) - 1);
                long dst = ((long)((z * 8 + t) * 256 + c0 + cc) << 12)
                         + (((ohi << lp) + pi) << 6) + (owi << lp) + pj;
                *(__half2*)(out + dst) = __floats2half2_rn(acc[mi][ni][hf*2], acc[mi][ni][hf*2 + 1]);
            }
        }
    }
}

// ============================================================================
// fp16 mma 32x32 NT split-K (P=32 scores): 2 warps, cross-warp smem reduce
// ============================================================================
__global__ void __launch_bounds__(64) hgemm32_kernel(
    const __half* __restrict__ A, const __half* __restrict__ B, float* __restrict__ C,
    int K, int splitk)
{
    __shared__ __half Qs[32 * 136];
    __shared__ __half Ks[32 * 136];
    __shared__ float buf[32][33];
    const int tid = threadIdx.x;
    const int lane = tid & 31, wrp = tid >> 5;
    const int z = blockIdx.z, bat = z / splitk, ks = z - bat * splitk;
    A += (long)bat * 32 * K;
    B += (long)bat * 32 * K;
    const int kchunk = K / splitk, kbeg = ks * kchunk;

    float acc[2][4][4] = {};
    for (int k0 = kbeg; k0 < kbeg + kchunk; k0 += 128) {
        __syncthreads();
#pragma unroll
        for (int i = 0; i < 8; i++) {
            int u = i * 64 + tid;
            int row = u >> 4, seg = (u & 15) * 8;
            *(uint4*)(Qs + row * 136 + seg) = *(const uint4*)(A + (long)row * K + k0 + seg);
            *(uint4*)(Ks + row * 136 + seg) = *(const uint4*)(B + (long)row * K + k0 + seg);
        }
        __syncthreads();
        for (int s = wrp; s < 8; s += 2) {
            const int kc = s * 16;
            uint32_t a[2][4], b[4][2];
            {
                const int arow = ((lane >> 3) & 1) * 8 + (lane & 7);
                const int akc  = kc + (lane >> 4) * 8;
                ldsm4(a[0], Qs + arow * 136 + akc);
                ldsm4(a[1], Qs + (arow + 16) * 136 + akc);
            }
            {
                const int bkc = kc + ((lane >> 3) & 1) * 8;
#pragma unroll
                for (int ni2 = 0; ni2 < 2; ni2++) {
                    const int brow = ni2 * 16 + ((lane >> 4) & 1) * 8 + (lane & 7);
                    uint32_t r[4];
                    ldsm4(r, Ks + brow * 136 + bkc);
                    b[2*ni2    ][0] = r[0]; b[2*ni2    ][1] = r[1];
                    b[2*ni2 + 1][0] = r[2]; b[2*ni2 + 1][1] = r[3];
                }
            }
#pragma unroll
            for (int mi = 0; mi < 2; mi++)
#pragma unroll
                for (int ni = 0; ni < 4; ni++)
                    mma16(acc[mi][ni], a[mi], b[ni]);
        }
    }

    const int rr = lane >> 2, cc = (lane & 3) * 2;
    if (wrp == 0) {
#pragma unroll
        for (int mi = 0; mi < 2; mi++)
#pragma unroll
            for (int ni = 0; ni < 4; ni++) {
                buf[mi*16 + rr    ][ni*8 + cc]     = acc[mi][ni][0];
                buf[mi*16 + rr    ][ni*8 + cc + 1] = acc[mi][ni][1];
                buf[mi*16 + rr + 8][ni*8 + cc]     = acc[mi][ni][2];
                buf[mi*16 + rr + 8][ni*8 + cc + 1] = acc[mi][ni][3];
            }
    }
    __syncthreads();
    if (wrp == 1) {
#pragma unroll
        for (int mi = 0; mi < 2; mi++)
#pragma unroll
            for (int ni = 0; ni < 4; ni++) {
                buf[mi*16 + rr    ][ni*8 + cc]     += acc[mi][ni][0];
                buf[mi*16 + rr    ][ni*8 + cc + 1] += acc[mi][ni][1];
                buf[mi*16 + rr + 8][ni*8 + cc]     += acc[mi][ni][2];
                buf[mi*16 + rr + 8][ni*8 + cc + 1] += acc[mi][ni][3];
            }
    }
    __syncthreads();
    float* Cz = C + (long)z * 1024;
    for (int i = tid; i < 1024; i += 64)
        Cz[i] = buf[i >> 5][i & 31];
}

__global__ void reduce_splitk_kernel(const float* __restrict__ part, float* __restrict__ S,
                                     int per, int splitk)
{
    long idx = (long)blockIdx.x * 256 + threadIdx.x;
    int b = (int)(idx / per);
    int r = (int)(idx - (long)b * per);
    float s = 0.f;
    for (int ks = 0; ks < splitk; ks++)
        s += part[(long)(b * splitk + ks) * per + r];
    S[idx] = s;
}

// ===================== SIMT AV for P=32 (M=32, half V), half out ==================
__global__ void __launch_bounds__(256) gemm_av32_kernel(
    const float* __restrict__ A, const __half* __restrict__ B, __half* __restrict__ out,
    int n, int d, int lp, int c0)
{
    const int z = blockIdx.z;
    A += (long)z * n * n;
    B += (long)z * n * d;
    const int m0 = blockIdx.y * 64, n0 = blockIdx.x * 64;
    __shared__ __align__(16) float As[16][68];
    __shared__ __align__(16) float Bs[16][64];
    const int tid = threadIdx.x;
    const int tx = tid & 15, ty = tid >> 4;
    float acc[4][4] = {};
    for (int k0 = 0; k0 < n; k0 += 16) {
#pragma unroll
        for (int it = 0; it < 4; it++) {
            int id = tid + it * 256;
            int m = id >> 4, kk = id & 15;
            As[kk][m] = (m0 + m < n) ? A[(long)(m0 + m) * n + k0 + kk] : 0.f;
        }
#pragma unroll
        for (int it = 0; it < 4; it++) {
            int id = tid + it * 256;
            int kk = id >> 6, nnn = id & 63;
            Bs[kk][nnn] = __half2float(B[(long)(k0 + kk) * d + n0 + nnn]);
        }
        __syncthreads();
#pragma unroll
        for (int kk = 0; kk < 16; kk++) {
            float4 a4 = *(const float4*)&As[kk][ty * 4];
            float4 b4 = *(const float4*)&Bs[kk][tx * 4];
            float ar[4] = {a4.x, a4.y, a4.z, a4.w};
            float br[4] = {b4.x, b4.y, b4.z, b4.w};
#pragma unroll
            for (int i = 0; i < 4; i++)
#pragma unroll
                for (int j = 0; j < 4; j++)
                    acc[i][j] += ar[i] * br[j];
        }
        __syncthreads();
    }
    const int lo = 6 - lp, o = 1 << lo, P = 1 << lp;
#pragma unroll
    for (int i = 0; i < 4; i++) {
        int m = m0 + ty * 4 + i;
        if (m >= n) continue;
        int t = m >> (2 * lo);
        int r = m & ((1 << (2 * lo)) - 1);
        int ohi = r >> lo, owi = r & (o - 1);
        int col = n0 + tx * 4;
        int cc = col >> (2 * lp);
        int rr = col & (P * P - 1);
        int pi = rr >> lp, pj = rr & (P - 1);
        long dst = ((long)((z * 8 + t) * 256 + c0 + cc) << 12)
                 + (((ohi << lp) + pi) << 6) + (owi << lp) + pj;
        *(__half2*)(out + dst)     = __floats2half2_rn(acc[i][0], acc[i][1]);
        *(__half2*)(out + dst + 2) = __floats2half2_rn(acc[i][2], acc[i][3]);
    }
}

// ===================== softmax (row-wise, scale folded in) ========================
__global__ void softmax_kernel(float* __restrict__ S, int n, float scale)
{
    __shared__ float buf[2048];
    __shared__ float red[256];
    const long row = blockIdx.x;
    float* p = S + row * (long)n;
    const int tid = threadIdx.x;
    float m = -1e30f;
    for (int i = tid; i < n; i += 256) { float v = p[i] * scale; buf[i] = v; m = fmaxf(m, v); }
    red[tid] = m; __syncthreads();
    for (int s = 128; s > 0; s >>= 1) { if (tid < s) red[tid] = fmaxf(red[tid], red[tid + s]); __syncthreads(); }
    m = red[0]; __syncthreads();
    float sum = 0.f;
    for (int i = tid; i < n; i += 256) { float e = expf(buf[i] - m); buf[i] = e; sum += e; }
    red[tid] = sum; __syncthreads();
    for (int s = 128; s > 0; s >>= 1) { if (tid < s) red[tid] += red[tid + s]; __syncthreads(); }
    float inv = 1.f / red[0];
    for (int i = tid; i < n; i += 256) p[i] = buf[i] * inv;
}

// ===================== launcher ===================================================
extern "C" void kernel_launch(void* const* d_in, const int* in_sizes, int n_in,
                              void* d_out, int out_size)
{
    const float* xs  = (const float*)d_in[0];
    const float* Wq  = (const float*)d_in[2];
    const float* bq  = (const float*)d_in[3];
    const float* Wk  = (const float*)d_in[4];
    const float* bk  = (const float*)d_in[5];
    const float* Wv  = (const float*)d_in[6];
    const float* bv  = (const float*)d_in[7];
    const float* Wl  = (const float*)d_in[8];
    const float* bl  = (const float*)d_in[9];
    const float* Wf1 = (const float*)d_in[10];
    const float* bf1 = (const float*)d_in[11];
    const float* Wf2 = (const float*)d_in[12];
    const float* bf2 = (const float*)d_in[13];
    float* out = (float*)d_out;

    __half *gQp, *gKp, *gVp, *gXsh, *gAtth, *gXs1h, *gFfh;
    __half *gWqh, *gWkh, *gWvh, *gWlh, *gWf1h, *gWf2h;
    float *gS, *gPart, *gXs1;
    cudaGetSymbolAddress((void**)&gQp,   g_Qp);
    cudaGetSymbolAddress((void**)&gKp,   g_Kp);
    cudaGetSymbolAddress((void**)&gVp,   g_Vp);
    cudaGetSymbolAddress((void**)&gS,    g_S);
    cudaGetSymbolAddress((void**)&gPart, g_part);
    cudaGetSymbolAddress((void**)&gXs1,  g_xs1);
    cudaGetSymbolAddress((void**)&gXsh,  g_xsh);
    cudaGetSymbolAddress((void**)&gAtth, g_atth);
    cudaGetSymbolAddress((void**)&gXs1h, g_xs1h);
    cudaGetSymbolAddress((void**)&gFfh,  g_ffh);
    cudaGetSymbolAddress((void**)&gWqh,  g_Wqh);
    cudaGetSymbolAddress((void**)&gWkh,  g_Wkh);
    cudaGetSymbolAddress((void**)&gWvh,  g_Wvh);
    cudaGetSymbolAddress((void**)&gWlh,  g_Wlh);
    cudaGetSymbolAddress((void**)&gWf1h, g_Wf1h);
    cudaGetSymbolAddress((void**)&gWf2h, g_Wf2h);

    cudaFuncSetAttribute(hconv3_kernel,
                         cudaFuncAttributeMaxDynamicSharedMemorySize, H3_SMEM);

    dim3 blk(256);
    dim3 qgrid(NIMG * 32, 2);
    dim3 cgrid3(NIMG * 16, 2);

    // pre-convert inputs + weights (convs: transpose to tap-major)
    f2h_kernel<<<16384, blk>>>(xs,  gXsh);
    f2h_kernel<<<64,    blk>>>(Wq,  gWqh);
    f2h_kernel<<<64,    blk>>>(Wk,  gWkh);
    f2h_kernel<<<64,    blk>>>(Wv,  gWvh);
    wtrans_kernel<<<2304, blk>>>(Wl,  gWlh);
    wtrans_kernel<<<2304, blk>>>(Wf1, gWf1h);
    wtrans_kernel<<<2304, blk>>>(Wf2, gWf2h);

    // QKV projections -> patchified half buffers (bias fused)
    hconv2_kernel<<<qgrid, blk>>>(gXsh, gWqh, bq, gQp);
    hconv2_kernel<<<qgrid, blk>>>(gXsh, gWkh, bk, gKp);
    hconv2_kernel<<<qgrid, blk>>>(gXsh, gWvh, bv, gVp);

    // ---- P=32 (n=32, d=65536) ----
    {
        const int n = 32, d = 65536, splitk = 256;
        hgemm32_kernel<<<dim3(1, 1, 2 * splitk), 64>>>(gQp, gKp, gPart, d, splitk);
        reduce_splitk_kernel<<<(2 * n * n) / 256, blk>>>(gPart, gS, n * n, splitk);
        softmax_kernel<<<2 * n, blk>>>(gS, n, 1.0f / 256.0f);
        gemm_av32_kernel<<<dim3(d / 64, 1, 2), blk>>>(gS, gVp, gAtth, n, d, 5, 0);
    }
    // ---- P=16 (n=128, d=16384) ----
    {
        const int n = 128, d = 16384, splitk = 64;
        const long soff = 4194304;
        hgemm_nt_kernel<<<dim3(1, 1, 2 * splitk), blk>>>(
            gQp + soff, gKp + soff, gPart, n, d, splitk, (long)n * d, (long)n * n);
        reduce_splitk_kernel<<<(2 * n * n) / 256, blk>>>(gPart, gS, n * n, splitk);
        softmax_kernel<<<2 * n, blk>>>(gS, n, 1.0f / 128.0f);
        hgemm_av_kernel<<<dim3(d / 128, n / 128, 2), blk>>>(gS, gVp + soff, gAtth, n, d, 4, 64);
    }
    // ---- P=8 (n=512, d=4096) ----
    {
        const int n = 512, d = 4096, splitk = 8;
        const long soff = 2L * 4194304;
        hgemm_nt_kernel<<<dim3(n / 128, n / 128, 2 * splitk), blk>>>(
            gQp + soff, gKp + soff, gPart, n, d, splitk, (long)n * d, (long)n * n);
        reduce_splitk_kernel<<<(2 * n * n) / 256, blk>>>(gPart, gS, n * n, splitk);
        softmax_kernel<<<2 * n, blk>>>(gS, n, 1.0f / 64.0f);
        hgemm_av_kernel<<<dim3(d / 128, n / 128, 2), blk>>>(gS, gVp + soff, gAtth, n, d, 3, 128);
    }
    // ---- P=4 (n=2048, d=1024) ----
    {
        const int n = 2048, d = 1024;
        const long soff = 3L * 4194304;
        hgemm_nt_kernel<<<dim3(n / 128, n / 128, 2), blk>>>(
            gQp + soff, gKp + soff, gS, n, d, 1, (long)n * d, (long)n * n);
        softmax_kernel<<<2 * n, blk>>>(gS, n, 1.0f / 32.0f);
        hgemm_av_kernel<<<dim3(d / 128, n / 128, 2), blk>>>(gS, gVp + soff, gAtth, n, d, 2, 192);
    }

    // convs: 256-pixel tiles (hconv3)
    hconv3_kernel<<<cgrid3, 512, H3_SMEM>>>(gAtth, gWlh,  bl,  xs,   gXs1, gXs1h, 1, 1);
    hconv3_kernel<<<cgrid3, 512, H3_SMEM>>>(gXs1h, gWf1h, bf1, nullptr, nullptr, gFfh, 1, 0);
    hconv3_kernel<<<cgrid3, 512, H3_SMEM>>>(gFfh,  gWf2h, bf2, gXs1, out,  nullptr, 2, 1);
}

// round 9
// speedup vs baseline: 1.2260x; 1.2260x over previous
#include <cuda_runtime.h>
#include <cuda_fp16.h>
#include <math.h>
#include <stdint.h>

#define NIMG 16
#define CCH 256
#define NPIX 4096            // 64*64

// ---- scratch (static device globals; no allocation) ----
__device__ __half g_Qp[16777216];
__device__ __half g_Kp[16777216];
__device__ __half g_Vp[16777216];
__device__ float  g_S[2*2048*2048];
__device__ float  g_part[8388608];
__device__ float  g_xs1[NIMG*CCH*NPIX];
__device__ __half g_xsh [NIMG*CCH*NPIX];
__device__ __half g_atth[NIMG*CCH*NPIX];
__device__ __half g_xs1h[NIMG*CCH*NPIX];
__device__ __half g_ffh [NIMG*CCH*NPIX];
__device__ __half g_Wqh[65536], g_Wkh[65536], g_Wvh[65536];
__device__ __half g_Wlh[589824], g_Wf1h[589824], g_Wf2h[589824];   // tap-major

// ============================================================================
// helpers
// ============================================================================
__device__ __forceinline__ void mma16(float* d, const uint32_t* a, const uint32_t* b) {
    asm volatile(
        "mma.sync.aligned.m16n8k16.row.col.f32.f16.f16.f32 "
        "{%0,%1,%2,%3}, {%4,%5,%6,%7}, {%8,%9}, {%0,%1,%2,%3};"
        : "+f"(d[0]), "+f"(d[1]), "+f"(d[2]), "+f"(d[3])
        : "r"(a[0]), "r"(a[1]), "r"(a[2]), "r"(a[3]), "r"(b[0]), "r"(b[1]));
}

__device__ __forceinline__ void ldsm4(uint32_t* r, const void* p) {
    uint32_t addr = (uint32_t)__cvta_generic_to_shared(p);
    asm volatile("ldmatrix.sync.aligned.m8n8.x4.shared.b16 {%0,%1,%2,%3}, [%4];"
        : "=r"(r[0]), "=r"(r[1]), "=r"(r[2]), "=r"(r[3]) : "r"(addr));
}

__device__ __forceinline__ void ldsm4t(uint32_t* r, const void* p) {
    uint32_t addr = (uint32_t)__cvta_generic_to_shared(p);
    asm volatile("ldmatrix.sync.aligned.m8n8.x4.trans.shared.b16 {%0,%1,%2,%3}, [%4];"
        : "=r"(r[0]), "=r"(r[1]), "=r"(r[2]), "=r"(r[3]) : "r"(addr));
}

__device__ __forceinline__ uint32_t pack_h2(float a, float b) {
    __half2 h = __floats2half2_rn(a, b);
    return *(uint32_t*)&h;
}

__device__ __forceinline__ void cpa16(uint32_t dst, const void* src, unsigned sz) {
    asm volatile("cp.async.ca.shared.global [%0], [%1], 16, %2;"
                 :: "r"(dst), "l"(src), "r"(sz) : "memory");
}
__device__ __forceinline__ void cpcommit() {
    asm volatile("cp.async.commit_group;" ::: "memory");
}
template <int N>
__device__ __forceinline__ void cpwait() {
    asm volatile("cp.async.wait_group %0;" :: "n"(N) : "memory");
}

// f32 -> f16 bulk convert (exact multiples of 1024 elems)
__global__ void f2h_kernel(const float* __restrict__ src, __half* __restrict__ dst) {
    long i = ((long)blockIdx.x * 256 + threadIdx.x) * 4;
    float4 v = *(const float4*)(src + i);
    *(uint32_t*)(dst + i)     = pack_h2(v.x, v.y);
    *(uint32_t*)(dst + i + 2) = pack_h2(v.z, v.w);
}

// conv weight transpose+convert: W[oc][c][tap] f32 -> Wt2[oc][tap][c] half
__global__ void wtrans_kernel(const float* __restrict__ W, __half* __restrict__ Wt2) {
    int idx = blockIdx.x * 256 + threadIdx.x;
    int oc = idx / 2304, r = idx - oc * 2304;
    int tap = r >> 8, c = r & 255;
    Wt2[idx] = __float2half(W[oc * 2304 + c * 9 + tap]);
}

// scatter index into patchified buffer: scale = oc>>6
__device__ __forceinline__ long pat_index(int img, int oc, int pix) {
    int s  = oc >> 6, cc = oc & 63;
    int lp = 5 - s;
    int lo = 1 + s;
    int Pm = (1 << lp) - 1;
    int y = pix >> 6, x = pix & 63;
    int ohi = y >> lp, pi = y & Pm, owi = x >> lp, pj = x & Pm;
    int t = img & 7, b = img >> 3;
    int nn = (t << (2*lo)) + (ohi << lo) + owi;
    int dd = (cc << (2*lp)) + (pi << lp) + pj;
    return (long)s * 4194304 + (long)b * 2097152 + (long)nn * (64 << (2*lp)) + dd;
}

// ============================================================================
// hconv2 (ks==1): QKV projection, cp.async pipelined, 256 threads
// ============================================================================
__global__ void __launch_bounds__(256, 2) hconv2_kernel(
    const __half* __restrict__ in, const __half* __restrict__ Wt,
    const float* __restrict__ bias, __half* __restrict__ outh_pat)
{
    __shared__ __half A2[2 * 128 * 40];
    __shared__ __half B2[2 * 32 * 136];

    const int tid = threadIdx.x;
    const int lane = tid & 31, wid = tid >> 5;
    const int wm = wid & 1, wn = wid >> 1;
    const int img = blockIdx.x >> 5;
    const int p0 = (blockIdx.x & 31) * 128;
    const int m0 = blockIdx.y * 128;
    const __half* inimg = in + (long)img * CCH * NPIX;

    const uint32_t sA2 = (uint32_t)__cvta_generic_to_shared(A2);
    const uint32_t sB2 = (uint32_t)__cvta_generic_to_shared(B2);

#define ISSUE1(KCN, NB)                                                         \
    {                                                                           \
        const int k0n = (KCN) * 32;                                             \
        {                                                                       \
            int row = tid >> 1, seg = (tid & 1) * 16;                           \
            const __half* src = Wt + (long)(m0 + row) * 256 + k0n + seg;        \
            uint32_t dst = sA2 + (uint32_t)(((NB) * 5120 + row * 40 + seg) * 2);\
            cpa16(dst, src, 16u); cpa16(dst + 16, src + 8, 16u);                \
        }                                                                       \
        {                                                                       \
            int k = tid >> 3, u = tid & 7;                                      \
            const __half* src = inimg + ((long)(k0n + k) << 12) + p0 + u * 8;   \
            uint32_t dst = sB2 + (uint32_t)(((NB) * 4352 + k * 136 + u * 8) * 2); \
            cpa16(dst, src, 16u);                                               \
            cpa16(dst + 128, src + 64, 16u);                                    \
        }                                                                       \
        cpcommit();                                                             \
    }

    float acc[4][4][4] = {};
    ISSUE1(0, 0);

    for (int kc = 0; kc < 8; kc++) {
        cpwait<0>();
        __syncthreads();
        if (kc + 1 < 8) ISSUE1(kc + 1, (kc + 1) & 1);

        const __half* Ap = A2 + (kc & 1) * 5120;
        const __half* Bp = B2 + (kc & 1) * 4352;
#pragma unroll
        for (int kstep = 0; kstep < 2; kstep++) {
            uint32_t a[4][4], b[4][2];
            {
                const int arow = wm * 64 + ((lane >> 3) & 1) * 8 + (lane & 7);
                const int akc  = kstep * 16 + (lane >> 4) * 8;
#pragma unroll
                for (int mi = 0; mi < 4; mi++)
                    ldsm4(a[mi], Ap + (arow + mi * 16) * 40 + akc);
            }
            {
                const int brow = kstep * 16 + (lane & 7) + ((lane >> 3) & 1) * 8;
#pragma unroll
                for (int ni2 = 0; ni2 < 2; ni2++) {
                    const int bcol = wn * 32 + ni2 * 16 + ((lane >> 4) & 1) * 8;
                    uint32_t r[4];
                    ldsm4t(r, Bp + brow * 136 + bcol);
                    b[2*ni2    ][0] = r[0]; b[2*ni2    ][1] = r[1];
                    b[2*ni2 + 1][0] = r[2]; b[2*ni2 + 1][1] = r[3];
                }
            }
#pragma unroll
            for (int mi = 0; mi < 4; mi++)
#pragma unroll
                for (int ni = 0; ni < 4; ni++)
                    mma16(acc[mi][ni], a[mi], b[ni]);
        }
        __syncthreads();
    }
#undef ISSUE1

    const int orow = m0 + wm * 64 + (lane >> 2);
    const int ocol = p0 + wn * 32 + (lane & 3) * 2;
#pragma unroll
    for (int mi = 0; mi < 4; mi++) {
        const int oca = orow + mi * 16, ocb = oca + 8;
        const float ba = bias[oca], bb = bias[ocb];
#pragma unroll
        for (int ni = 0; ni < 4; ni++) {
            const int n = ocol + ni * 8;
            long ia = pat_index(img, oca, n);
            long ib = pat_index(img, ocb, n);
            *(__half2*)(outh_pat + ia) = __floats2half2_rn(acc[mi][ni][0] + ba, acc[mi][ni][1] + ba);
            *(__half2*)(outh_pat + ib) = __floats2half2_rn(acc[mi][ni][2] + bb, acc[mi][ni][3] + bb);
        }
    }
}

// ============================================================================
// hconvK: 3x3 conv, tap-major K, 256 threads, M=128 x N=128 tile, K-chunk 64
//   dynamic smem (halves): A2[2*128*72] | Bs[64*136] | Strip[64*160]
// ============================================================================
#define HK_A2    0
#define HK_BS    18432
#define HK_STRIP (18432 + 8704)
#define HK_SMEM  ((18432 + 8704 + 10240) * 2)

__global__ void __launch_bounds__(256, 2) hconvK_kernel(
    const __half* __restrict__ in, const __half* __restrict__ Wt,
    const float* __restrict__ bias, const float* __restrict__ res,
    float* __restrict__ out, __half* __restrict__ outh_img,
    int dil, int addres)
{
    extern __shared__ __half sh[];
    __half* A2    = sh + HK_A2;
    __half* Bs    = sh + HK_BS;
    __half* Strip = sh + HK_STRIP;

    const int tid = threadIdx.x;
    const int lane = tid & 31, wid = tid >> 5;
    const int wm = wid & 1, wn = wid >> 1;
    const int img = blockIdx.x >> 5;
    const int p0 = (blockIdx.x & 31) * 128;
    const int y0 = p0 >> 6;                 // 2 image rows: y0, y0+1
    const int m0 = blockIdx.y * 128;
    const __half* inimg = in + (long)img * CCH * NPIX;

    const uint32_t sA2    = (uint32_t)__cvta_generic_to_shared(A2);
    const uint32_t sStrip = (uint32_t)__cvta_generic_to_shared(Strip);

    // zero strip halos once: 64 ch x 2 rows x 2 sides (8 halves each)
    {
        int c = tid >> 2, u = tid & 3, r = u >> 1, side = u & 1;
        *(uint4*)(Strip + c * 160 + r * 80 + side * 72) = make_uint4(0, 0, 0, 0);
    }

#define ISSUEK(KCN, NB)                                                          \
    {                                                                            \
        const int k0n = (KCN) * 64;                                              \
        {   /* A: 128 oc x 64 k */                                               \
            int row = tid >> 1, seg = (tid & 1) * 32;                            \
            const __half* src = Wt + (long)(m0 + row) * 2304 + k0n + seg;        \
            uint32_t dst = sA2 + (uint32_t)(((NB) * 9216 + row * 72 + seg) * 2); \
            cpa16(dst,      src,      16u);                                      \
            cpa16(dst + 16, src + 8,  16u);                                      \
            cpa16(dst + 32, src + 16, 16u);                                      \
            cpa16(dst + 48, src + 24, 16u);                                      \
        }                                                                        \
        {   /* strip: 64 ch x 2 rows x 64 px */                                  \
            int tapn = (KCN) >> 2;                                               \
            int c0 = (k0n) & 255;                                                \
            int dyd = (tapn / 3 - 1) * dil;                                      \
            int c = tid >> 2, u = tid & 3;                                       \
            int r = u >> 1, s = u & 1;                                           \
            int gy = y0 + r + dyd;                                               \
            unsigned ok = ((unsigned)gy < 64u) ? 16u : 0u;                       \
            int gyc = gy < 0 ? 0 : (gy > 63 ? 63 : gy);                          \
            const __half* src = inimg + ((long)(c0 + c) << 12) + (gyc << 6) + s * 32; \
            uint32_t dst = sStrip + (uint32_t)((c * 160 + r * 80 + 8 + s * 32) * 2);  \
            cpa16(dst,      src,      ok);                                       \
            cpa16(dst + 16, src + 8,  ok);                                       \
            cpa16(dst + 32, src + 16, ok);                                       \
            cpa16(dst + 48, src + 24, ok);                                       \
        }                                                                        \
        cpcommit();                                                              \
    }

    float acc[4][4][4] = {};
    ISSUEK(0, 0);

    for (int kc = 0; kc < 36; kc++) {
        cpwait<0>();
        __syncthreads();

        // build shifted B tile (64 k-rows x 128 px) from strip
        {
            const int tap = kc >> 2;
            const int dxd = (tap - (tap / 3) * 3 - 1) * dil;
            const int c = tid >> 2, u = tid & 3, prow = u >> 1, xseg = (u & 1) * 32;
            const uint32_t* rowp = (const uint32_t*)(Strip + c * 160 + prow * 80);
            const int h0 = 8 + dxd + xseg;
            uint32_t w[16];
            if (dxd & 1) {
                int k0 = (h0 - 1) >> 1;
                uint32_t prev = rowp[k0];
#pragma unroll
                for (int j = 0; j < 16; j++) {
                    uint32_t nxt = rowp[k0 + 1 + j];
                    w[j] = __funnelshift_r(prev, nxt, 16);
                    prev = nxt;
                }
            } else {
                int k0 = h0 >> 1;
#pragma unroll
                for (int j = 0; j < 16; j++) w[j] = rowp[k0 + j];
            }
            uint4* bd = (uint4*)(Bs + c * 136 + prow * 64 + xseg);
#pragma unroll
            for (int j = 0; j < 4; j++)
                bd[j] = make_uint4(w[4*j], w[4*j+1], w[4*j+2], w[4*j+3]);
        }
        __syncthreads();

        if (kc + 1 < 36) ISSUEK(kc + 1, (kc + 1) & 1);

        const __half* Ap = A2 + (kc & 1) * 9216;
#pragma unroll
        for (int kstep = 0; kstep < 4; kstep++) {
            uint32_t a[4][4], b[4][2];
            {
                const int arow = wm * 64 + ((lane >> 3) & 1) * 8 + (lane & 7);
                const int akc  = kstep * 16 + (lane >> 4) * 8;
#pragma unroll
                for (int mi = 0; mi < 4; mi++)
                    ldsm4(a[mi], Ap + (arow + mi * 16) * 72 + akc);
            }
            {
                const int brow = kstep * 16 + (lane & 7) + ((lane >> 3) & 1) * 8;
#pragma unroll
                for (int ni2 = 0; ni2 < 2; ni2++) {
                    const int bcol = wn * 32 + ni2 * 16 + ((lane >> 4) & 1) * 8;
                    uint32_t r[4];
                    ldsm4t(r, Bs + brow * 136 + bcol);
                    b[2*ni2    ][0] = r[0]; b[2*ni2    ][1] = r[1];
                    b[2*ni2 + 1][0] = r[2]; b[2*ni2 + 1][1] = r[3];
                }
            }
#pragma unroll
            for (int mi = 0; mi < 4; mi++)
#pragma unroll
                for (int ni = 0; ni < 4; ni++)
                    mma16(acc[mi][ni], a[mi], b[ni]);
        }
    }
#undef ISSUEK

    const int orow = m0 + wm * 64 + (lane >> 2);
    const int ocol = p0 + wn * 32 + (lane & 3) * 2;
#pragma unroll
    for (int mi = 0; mi < 4; mi++) {
        const int oca = orow + mi * 16;
        const int ocb = oca + 8;
        const float ba = bias[oca], bb = bias[ocb];
#pragma unroll
        for (int ni = 0; ni < 4; ni++) {
            const int n = ocol + ni * 8;
            long ia = ((long)img * 256 + oca) * NPIX + n;
            long ib = ((long)img * 256 + ocb) * NPIX + n;
            float v0 = acc[mi][ni][0] + ba, v1 = acc[mi][ni][1] + ba;
            float v2 = acc[mi][ni][2] + bb, v3 = acc[mi][ni][3] + bb;
            v0 = (v0 > 0.f) ? v0 : 0.2f * v0;
            v1 = (v1 > 0.f) ? v1 : 0.2f * v1;
            v2 = (v2 > 0.f) ? v2 : 0.2f * v2;
            v3 = (v3 > 0.f) ? v3 : 0.2f * v3;
            if (addres) {
                v0 += res[ia]; v1 += res[ia + 1];
                v2 += res[ib]; v3 += res[ib + 1];
            }
            if (out) {
                out[ia] = v0; out[ia + 1] = v1;
                out[ib] = v2; out[ib + 1] = v3;
            }
            if (outh_img) {
                *(__half2*)(outh_img + ia) = __floats2half2_rn(v0, v1);
                *(__half2*)(outh_img + ib) = __floats2half2_rn(v2, v3);
            }
        }
    }
}

// ============================================================================
// fp16 NT GEMM with deterministic split-K (scores), f32 out
// ============================================================================
__global__ void __launch_bounds__(256) hgemm_nt_kernel(
    const __half* __restrict__ A, const __half* __restrict__ B, float* __restrict__ C,
    int N, int K, int splitk, long sAB, long sC)
{
    __shared__ __half As[128 * 40];
    __shared__ __half Bs[128 * 40];
    const int tid = threadIdx.x;
    const int lane = tid & 31, wid = tid >> 5;
    const int wm = wid & 1, wn = wid >> 1;
    const int n0 = blockIdx.x * 128, m0 = blockIdx.y * 128;
    const int z = blockIdx.z, bat = z / splitk, ks = z - bat * splitk;
    A += (long)bat * sAB;
    B += (long)bat * sAB;
    C += (long)z * sC;
    const int kchunk = K / splitk, kbeg = ks * kchunk;
    const int wr = tid >> 1, wkh = (tid & 1) * 16;

    float acc[4][4][4] = {};
    for (int k0 = kbeg; k0 < kbeg + kchunk; k0 += 32) {
        __syncthreads();
        {
            const __half* sa = A + (long)(m0 + wr) * K + k0 + wkh;
            const __half* sb = B + (long)(n0 + wr) * K + k0 + wkh;
            *(uint4*)(As + wr * 40 + wkh)     = *(const uint4*)sa;
            *(uint4*)(As + wr * 40 + wkh + 8) = *(const uint4*)(sa + 8);
            *(uint4*)(Bs + wr * 40 + wkh)     = *(const uint4*)sb;
            *(uint4*)(Bs + wr * 40 + wkh + 8) = *(const uint4*)(sb + 8);
        }
        __syncthreads();
#pragma unroll
        for (int kstep = 0; kstep < 2; kstep++) {
            uint32_t a[4][4], b[4][2];
            {
                const int arow = wm * 64 + ((lane >> 3) & 1) * 8 + (lane & 7);
                const int akc  = kstep * 16 + (lane >> 4) * 8;
#pragma unroll
                for (int mi = 0; mi < 4; mi++)
                    ldsm4(a[mi], As + (arow + mi * 16) * 40 + akc);
            }
            {
                const int bkc = kstep * 16 + ((lane >> 3) & 1) * 8;
#pragma unroll
                for (int ni2 = 0; ni2 < 2; ni2++) {
                    const int brow = wn * 32 + ni2 * 16 + ((lane >> 4) & 1) * 8 + (lane & 7);
                    uint32_t r[4];
                    ldsm4(r, Bs + brow * 40 + bkc);
                    b[2*ni2    ][0] = r[0]; b[2*ni2    ][1] = r[1];
                    b[2*ni2 + 1][0] = r[2]; b[2*ni2 + 1][1] = r[3];
                }
            }
#pragma unroll
            for (int mi = 0; mi < 4; mi++)
#pragma unroll
                for (int ni = 0; ni < 4; ni++)
                    mma16(acc[mi][ni], a[mi], b[ni]);
        }
    }
    const int orow = m0 + wm * 64 + (lane >> 2);
    const int ocol = n0 + wn * 32 + (lane & 3) * 2;
#pragma unroll
    for (int mi = 0; mi < 4; mi++) {
        long ra = (long)(orow + mi * 16) * N;
        long rb = (long)(orow + mi * 16 + 8) * N;
#pragma unroll
        for (int ni = 0; ni < 4; ni++) {
            int n = ocol + ni * 8;
            C[ra + n] = acc[mi][ni][0]; C[ra + n + 1] = acc[mi][ni][1];
            C[rb + n] = acc[mi][ni][2]; C[rb + n + 1] = acc[mi][ni][3];
        }
    }
}

// ============================================================================
// fp16 AV GEMM (NN via trans-ldmatrix B), scatter epilogue -> half image
// ============================================================================
__global__ void __launch_bounds__(256) hgemm_av_kernel(
    const float* __restrict__ S, const __half* __restrict__ V, __half* __restrict__ out,
    int n, int d, int lp, int c0)
{
    __shared__ __half As[128 * 40];
    __shared__ __half Bs[32 * 136];
    const int tid = threadIdx.x;
    const int lane = tid & 31, wid = tid >> 5;
    const int wm = wid & 1, wn = wid >> 1;
    const int z = blockIdx.z;
    S += (long)z * n * n;
    V += (long)z * n * d;
    const int n0 = blockIdx.x * 128;
    const int m0 = blockIdx.y * 128;
    const int wr = tid >> 1, wkh = (tid & 1) * 16;
    const int bk = tid >> 3, bn0 = (tid & 7) * 16;

    float acc[4][4][4] = {};
    for (int k0 = 0; k0 < n; k0 += 32) {
        __syncthreads();
        {
            const float* sa = S + (long)(m0 + wr) * n + k0 + wkh;
            uint32_t* ad = (uint32_t*)(As + wr * 40 + wkh);
#pragma unroll
            for (int i4 = 0; i4 < 4; i4++) {
                float4 v = *(const float4*)(sa + i4 * 4);
                ad[i4*2 + 0] = pack_h2(v.x, v.y);
                ad[i4*2 + 1] = pack_h2(v.z, v.w);
            }
            const __half* sb = V + (long)(k0 + bk) * d + n0 + bn0;
            *(uint4*)(Bs + bk * 136 + bn0)     = *(const uint4*)sb;
            *(uint4*)(Bs + bk * 136 + bn0 + 8) = *(const uint4*)(sb + 8);
        }
        __syncthreads();
#pragma unroll
        for (int kstep = 0; kstep < 2; kstep++) {
            uint32_t a[4][4], b[4][2];
            {
                const int arow = wm * 64 + ((lane >> 3) & 1) * 8 + (lane & 7);
                const int akc  = kstep * 16 + (lane >> 4) * 8;
#pragma unroll
                for (int mi = 0; mi < 4; mi++)
                    ldsm4(a[mi], As + (arow + mi * 16) * 40 + akc);
            }
            {
                const int brow = kstep * 16 + (lane & 7) + ((lane >> 3) & 1) * 8;
#pragma unroll
                for (int ni2 = 0; ni2 < 2; ni2++) {
                    const int bcol = wn * 32 + ni2 * 16 + ((lane >> 4) & 1) * 8;
                    uint32_t r[4];
                    ldsm4t(r, Bs + brow * 136 + bcol);
                    b[2*ni2    ][0] = r[0]; b[2*ni2    ][1] = r[1];
                    b[2*ni2 + 1][0] = r[2]; b[2*ni2 + 1][1] = r[3];
                }
            }
#pragma unroll
            for (int mi = 0; mi < 4; mi++)
#pragma unroll
                for (int ni = 0; ni < 4; ni++)
                    mma16(acc[mi][ni], a[mi], b[ni]);
        }
    }

    const int lo = 6 - lp;
    const int orow = m0 + wm * 64 + (lane >> 2);
    const int ocol = n0 + wn * 32 + (lane & 3) * 2;
#pragma unroll
    for (int mi = 0; mi < 4; mi++) {
#pragma unroll
        for (int hf = 0; hf < 2; hf++) {
            const int m = orow + mi * 16 + hf * 8;
            const int t = m >> (2 * lo);
            const int r = m & ((1 << (2 * lo)) - 1);
            const int ohi = r >> lo, owi = r & ((1 << lo) - 1);
#pragma unroll
            for (int ni = 0; ni < 4; ni++) {
                const int col = ocol + ni * 8;
                const int cc = col >> (2 * lp);
                const int rr = col & ((1 << (2 * lp)) - 1);
                const int pi = rr >> lp, pj = rr & ((1 << lp) - 1);
                long dst = ((long)((z * 8 + t) * 256 + c0 + cc) << 12)
                         + (((ohi << lp) + pi) << 6) + (owi << lp) + pj;
                *(__half2*)(out + dst) = __floats2half2_rn(acc[mi][ni][hf*2], acc[mi][ni][hf*2 + 1]);
            }
        }
    }
}

// ============================================================================
// fp16 mma 32x32 NT split-K (P=32 scores): 2 warps, cross-warp smem reduce
// ============================================================================
__global__ void __launch_bounds__(64) hgemm32_kernel(
    const __half* __restrict__ A, const __half* __restrict__ B, float* __restrict__ C,
    int K, int splitk)
{
    __shared__ __half Qs[32 * 136];
    __shared__ __half Ks[32 * 136];
    __shared__ float buf[32][33];
    const int tid = threadIdx.x;
    const int lane = tid & 31, wrp = tid >> 5;
    const int z = blockIdx.z, bat = z / splitk, ks = z - bat * splitk;
    A += (long)bat * 32 * K;
    B += (long)bat * 32 * K;
    const int kchunk = K / splitk, kbeg = ks * kchunk;

    float acc[2][4][4] = {};
    for (int k0 = kbeg; k0 < kbeg + kchunk; k0 += 128) {
        __syncthreads();
#pragma unroll
        for (int i = 0; i < 8; i++) {
            int u = i * 64 + tid;
            int row = u >> 4, seg = (u & 15) * 8;
            *(uint4*)(Qs + row * 136 + seg) = *(const uint4*)(A + (long)row * K + k0 + seg);
            *(uint4*)(Ks + row * 136 + seg) = *(const uint4*)(B + (long)row * K + k0 + seg);
        }
        __syncthreads();
        for (int s = wrp; s < 8; s += 2) {
            const int kc = s * 16;
            uint32_t a[2][4], b[4][2];
            {
                const int arow = ((lane >> 3) & 1) * 8 + (lane & 7);
                const int akc  = kc + (lane >> 4) * 8;
                ldsm4(a[0], Qs + arow * 136 + akc);
                ldsm4(a[1], Qs + (arow + 16) * 136 + akc);
            }
            {
                const int bkc = kc + ((lane >> 3) & 1) * 8;
#pragma unroll
                for (int ni2 = 0; ni2 < 2; ni2++) {
                    const int brow = ni2 * 16 + ((lane >> 4) & 1) * 8 + (lane & 7);
                    uint32_t r[4];
                    ldsm4(r, Ks + brow * 136 + bkc);
                    b[2*ni2    ][0] = r[0]; b[2*ni2    ][1] = r[1];
                    b[2*ni2 + 1][0] = r[2]; b[2*ni2 + 1][1] = r[3];
                }
            }
#pragma unroll
            for (int mi = 0; mi < 2; mi++)
#pragma unroll
                for (int ni = 0; ni < 4; ni++)
                    mma16(acc[mi][ni], a[mi], b[ni]);
        }
    }

    const int rr = lane >> 2, cc = (lane & 3) * 2;
    if (wrp == 0) {
#pragma unroll
        for (int mi = 0; mi < 2; mi++)
#pragma unroll
            for (int ni = 0; ni < 4; ni++) {
                buf[mi*16 + rr    ][ni*8 + cc]     = acc[mi][ni][0];
                buf[mi*16 + rr    ][ni*8 + cc + 1] = acc[mi][ni][1];
                buf[mi*16 + rr + 8][ni*8 + cc]     = acc[mi][ni][2];
                buf[mi*16 + rr + 8][ni*8 + cc + 1] = acc[mi][ni][3];
            }
    }
    __syncthreads();
    if (wrp == 1) {
#pragma unroll
        for (int mi = 0; mi < 2; mi++)
#pragma unroll
            for (int ni = 0; ni < 4; ni++) {
                buf[mi*16 + rr    ][ni*8 + cc]     += acc[mi][ni][0];
                buf[mi*16 + rr    ][ni*8 + cc + 1] += acc[mi][ni][1];
                buf[mi*16 + rr + 8][ni*8 + cc]     += acc[mi][ni][2];
                buf[mi*16 + rr + 8][ni*8 + cc + 1] += acc[mi][ni][3];
            }
    }
    __syncthreads();
    float* Cz = C + (long)z * 1024;
    for (int i = tid; i < 1024; i += 64)
        Cz[i] = buf[i >> 5][i & 31];
}

__global__ void reduce_splitk_kernel(const float* __restrict__ part, float* __restrict__ S,
                                     int per, int splitk)
{
    long idx = (long)blockIdx.x * 256 + threadIdx.x;
    int b = (int)(idx / per);
    int r = (int)(idx - (long)b * per);
    float s = 0.f;
    for (int ks = 0; ks < splitk; ks++)
        s += part[(long)(b * splitk + ks) * per + r];
    S[idx] = s;
}

// ===================== SIMT AV for P=32 (M=32, half V), half out ==================
__global__ void __launch_bounds__(256) gemm_av32_kernel(
    const float* __restrict__ A, const __half* __restrict__ B, __half* __restrict__ out,
    int n, int d, int lp, int c0)
{
    const int z = blockIdx.z;
    A += (long)z * n * n;
    B += (long)z * n * d;
    const int m0 = blockIdx.y * 64, n0 = blockIdx.x * 64;
    __shared__ __align__(16) float As[16][68];
    __shared__ __align__(16) float Bs[16][64];
    const int tid = threadIdx.x;
    const int tx = tid & 15, ty = tid >> 4;
    float acc[4][4] = {};
    for (int k0 = 0; k0 < n; k0 += 16) {
#pragma unroll
        for (int it = 0; it < 4; it++) {
            int id = tid + it * 256;
            int m = id >> 4, kk = id & 15;
            As[kk][m] = (m0 + m < n) ? A[(long)(m0 + m) * n + k0 + kk] : 0.f;
        }
#pragma unroll
        for (int it = 0; it < 4; it++) {
            int id = tid + it * 256;
            int kk = id >> 6, nnn = id & 63;
            Bs[kk][nnn] = __half2float(B[(long)(k0 + kk) * d + n0 + nnn]);
        }
        __syncthreads();
#pragma unroll
        for (int kk = 0; kk < 16; kk++) {
            float4 a4 = *(const float4*)&As[kk][ty * 4];
            float4 b4 = *(const float4*)&Bs[kk][tx * 4];
            float ar[4] = {a4.x, a4.y, a4.z, a4.w};
            float br[4] = {b4.x, b4.y, b4.z, b4.w};
#pragma unroll
            for (int i = 0; i < 4; i++)
#pragma unroll
                for (int j = 0; j < 4; j++)
                    acc[i][j] += ar[i] * br[j];
        }
        __syncthreads();
    }
    const int lo = 6 - lp, o = 1 << lo, P = 1 << lp;
#pragma unroll
    for (int i = 0; i < 4; i++) {
        int m = m0 + ty * 4 + i;
        if (m >= n) continue;
        int t = m >> (2 * lo);
        int r = m & ((1 << (2 * lo)) - 1);
        int ohi = r >> lo, owi = r & (o - 1);
        int col = n0 + tx * 4;
        int cc = col >> (2 * lp);
        int rr = col & (P * P - 1);
        int pi = rr >> lp, pj = rr & (P - 1);
        long dst = ((long)((z * 8 + t) * 256 + c0 + cc) << 12)
                 + (((ohi << lp) + pi) << 6) + (owi << lp) + pj;
        *(__half2*)(out + dst)     = __floats2half2_rn(acc[i][0], acc[i][1]);
        *(__half2*)(out + dst + 2) = __floats2half2_rn(acc[i][2], acc[i][3]);
    }
}

// ===================== softmax (row-wise, scale folded in) ========================
__global__ void softmax_kernel(float* __restrict__ S, int n, float scale)
{
    __shared__ float buf[2048];
    __shared__ float red[256];
    const long row = blockIdx.x;
    float* p = S + row * (long)n;
    const int tid = threadIdx.x;
    float m = -1e30f;
    for (int i = tid; i < n; i += 256) { float v = p[i] * scale; buf[i] = v; m = fmaxf(m, v); }
    red[tid] = m; __syncthreads();
    for (int s = 128; s > 0; s >>= 1) { if (tid < s) red[tid] = fmaxf(red[tid], red[tid + s]); __syncthreads(); }
    m = red[0]; __syncthreads();
    float sum = 0.f;
    for (int i = tid; i < n; i += 256) { float e = expf(buf[i] - m); buf[i] = e; sum += e; }
    red[tid] = sum; __syncthreads();
    for (int s = 128; s > 0; s >>= 1) { if (tid < s) red[tid] += red[tid + s]; __syncthreads(); }
    float inv = 1.f / red[0];
    for (int i = tid; i < n; i += 256) p[i] = buf[i] * inv;
}

// ===================== launcher ===================================================
extern "C" void kernel_launch(void* const* d_in, const int* in_sizes, int n_in,
                              void* d_out, int out_size)
{
    const float* xs  = (const float*)d_in[0];
    const float* Wq  = (const float*)d_in[2];
    const float* bq  = (const float*)d_in[3];
    const float* Wk  = (const float*)d_in[4];
    const float* bk  = (const float*)d_in[5];
    const float* Wv  = (const float*)d_in[6];
    const float* bv  = (const float*)d_in[7];
    const float* Wl  = (const float*)d_in[8];
    const float* bl  = (const float*)d_in[9];
    const float* Wf1 = (const float*)d_in[10];
    const float* bf1 = (const float*)d_in[11];
    const float* Wf2 = (const float*)d_in[12];
    const float* bf2 = (const float*)d_in[13];
    float* out = (float*)d_out;

    __half *gQp, *gKp, *gVp, *gXsh, *gAtth, *gXs1h, *gFfh;
    __half *gWqh, *gWkh, *gWvh, *gWlh, *gWf1h, *gWf2h;
    float *gS, *gPart, *gXs1;
    cudaGetSymbolAddress((void**)&gQp,   g_Qp);
    cudaGetSymbolAddress((void**)&gKp,   g_Kp);
    cudaGetSymbolAddress((void**)&gVp,   g_Vp);
    cudaGetSymbolAddress((void**)&gS,    g_S);
    cudaGetSymbolAddress((void**)&gPart, g_part);
    cudaGetSymbolAddress((void**)&gXs1,  g_xs1);
    cudaGetSymbolAddress((void**)&gXsh,  g_xsh);
    cudaGetSymbolAddress((void**)&gAtth, g_atth);
    cudaGetSymbolAddress((void**)&gXs1h, g_xs1h);
    cudaGetSymbolAddress((void**)&gFfh,  g_ffh);
    cudaGetSymbolAddress((void**)&gWqh,  g_Wqh);
    cudaGetSymbolAddress((void**)&gWkh,  g_Wkh);
    cudaGetSymbolAddress((void**)&gWvh,  g_Wvh);
    cudaGetSymbolAddress((void**)&gWlh,  g_Wlh);
    cudaGetSymbolAddress((void**)&gWf1h, g_Wf1h);
    cudaGetSymbolAddress((void**)&gWf2h, g_Wf2h);

    cudaFuncSetAttribute(hconvK_kernel,
                         cudaFuncAttributeMaxDynamicSharedMemorySize, HK_SMEM);

    dim3 blk(256);
    dim3 qgrid(NIMG * 32, 2);

    // pre-convert inputs + weights (convs: transpose to tap-major)
    f2h_kernel<<<16384, blk>>>(xs,  gXsh);
    f2h_kernel<<<64,    blk>>>(Wq,  gWqh);
    f2h_kernel<<<64,    blk>>>(Wk,  gWkh);
    f2h_kernel<<<64,    blk>>>(Wv,  gWvh);
    wtrans_kernel<<<2304, blk>>>(Wl,  gWlh);
    wtrans_kernel<<<2304, blk>>>(Wf1, gWf1h);
    wtrans_kernel<<<2304, blk>>>(Wf2, gWf2h);

    // QKV projections -> patchified half buffers (bias fused)
    hconv2_kernel<<<qgrid, blk>>>(gXsh, gWqh, bq, gQp);
    hconv2_kernel<<<qgrid, blk>>>(gXsh, gWkh, bk, gKp);
    hconv2_kernel<<<qgrid, blk>>>(gXsh, gWvh, bv, gVp);

    // ---- P=32 (n=32, d=65536) ----
    {
        const int n = 32, d = 65536, splitk = 256;
        hgemm32_kernel<<<dim3(1, 1, 2 * splitk), 64>>>(gQp, gKp, gPart, d, splitk);
        reduce_splitk_kernel<<<(2 * n * n) / 256, blk>>>(gPart, gS, n * n, splitk);
        softmax_kernel<<<2 * n, blk>>>(gS, n, 1.0f / 256.0f);
        gemm_av32_kernel<<<dim3(d / 64, 1, 2), blk>>>(gS, gVp, gAtth, n, d, 5, 0);
    }
    // ---- P=16 (n=128, d=16384) ----
    {
        const int n = 128, d = 16384, splitk = 64;
        const long soff = 4194304;
        hgemm_nt_kernel<<<dim3(1, 1, 2 * splitk), blk>>>(
            gQp + soff, gKp + soff, gPart, n, d, splitk, (long)n * d, (long)n * n);
        reduce_splitk_kernel<<<(2 * n * n) / 256, blk>>>(gPart, gS, n * n, splitk);
        softmax_kernel<<<2 * n, blk>>>(gS, n, 1.0f / 128.0f);
        hgemm_av_kernel<<<dim3(d / 128, n / 128, 2), blk>>>(gS, gVp + soff, gAtth, n, d, 4, 64);
    }
    // ---- P=8 (n=512, d=4096) ----
    {
        const int n = 512, d = 4096, splitk = 8;
        const long soff = 2L * 4194304;
        hgemm_nt_kernel<<<dim3(n / 128, n / 128, 2 * splitk), blk>>>(
            gQp + soff, gKp + soff, gPart, n, d, splitk, (long)n * d, (long)n * n);
        reduce_splitk_kernel<<<(2 * n * n) / 256, blk>>>(gPart, gS, n * n, splitk);
        softmax_kernel<<<2 * n, blk>>>(gS, n, 1.0f / 64.0f);
        hgemm_av_kernel<<<dim3(d / 128, n / 128, 2), blk>>>(gS, gVp + soff, gAtth, n, d, 3, 128);
    }
    // ---- P=4 (n=2048, d=1024) ----
    {
        const int n = 2048, d = 1024;
        const long soff = 3L * 4194304;
        hgemm_nt_kernel<<<dim3(n / 128, n / 128, 2), blk>>>(
            gQp + soff, gKp + soff, gS, n, d, 1, (long)n * d, (long)n * n);
        softmax_kernel<<<2 * n, blk>>>(gS, n, 1.0f / 32.0f);
        hgemm_av_kernel<<<dim3(d / 128, n / 128, 2), blk>>>(gS, gVp + soff, gAtth, n, d, 2, 192);
    }

    // convs: 128-pixel tiles, K-chunk 64 (hconvK)
    hconvK_kernel<<<qgrid, blk, HK_SMEM>>>(gAtth, gWlh,  bl,  xs,      gXs1,    gXs1h, 1, 1);
    hconvK_kernel<<<qgrid, blk, HK_SMEM>>>(gXs1h, gWf1h, bf1, nullptr, nullptr, gFfh,  1, 0);
    hconvK_kernel<<<qgrid, blk, HK_SMEM>>>(gFfh,  gWf2h, bf2, gXs1,    out,     nullptr, 2, 1);
}